// round 5
// baseline (speedup 1.0000x reference)
#include <cuda_runtime.h>
#include <math.h>

// Scratch for per-node projections: P[n][0:16] = z[n] @ W1[0:128,:],
// P[n][16:32] = z[n] @ W1[128:256,:].  Sized for N up to 131072 (actual N=100000).
#define MAX_NODES (131072)
__device__ __align__(16) float g_P[(size_t)MAX_NODES * 32];

// Flag: 1 if edge_index is stored as int64 on device, 0 if int32.
__device__ int g_ei_is64;

// ---------------------------------------------------------------------------
// Kernel 0: detect edge_index storage dtype.
// If the buffer is int32, an int64 read in [0,N) would require the paired
// high word to be 0 (p ~ 1e-5 each); 64 hits in a row is impossible.
// All int64 reads stay within the first 8*min(64,E) bytes, which both
// layouts own.
// ---------------------------------------------------------------------------
__global__ void detect_kernel(const long long* __restrict__ ei, int E, int N)
{
    if (blockIdx.x == 0 && threadIdx.x == 0) {
        int is64 = 1;
        int cnt = E < 64 ? E : 64;
        for (int i = 0; i < cnt; i++) {
            long long v = ei[i];
            if (v < 0 || v >= (long long)N) { is64 = 0; break; }
        }
        g_ei_is64 = is64;
    }
}

// ---------------------------------------------------------------------------
// Kernel 1: per-node projection.  One thread per node, W1 staged in smem.
// ---------------------------------------------------------------------------
__global__ __launch_bounds__(256)
void proj_kernel(const float* __restrict__ z,
                 const float* __restrict__ W1,   // [256,16] row-major
                 int N)
{
    __shared__ float sW1[256 * 16];
    for (int i = threadIdx.x; i < 256 * 16; i += blockDim.x)
        sW1[i] = W1[i];
    __syncthreads();

    int n = blockIdx.x * blockDim.x + threadIdx.x;
    if (n >= N) return;

    const float4* z4 = reinterpret_cast<const float4*>(z) + (size_t)n * 32;

    float accT[16], accB[16];
#pragma unroll
    for (int j = 0; j < 16; j++) { accT[j] = 0.f; accB[j] = 0.f; }

#pragma unroll 4
    for (int i = 0; i < 32; i++) {
        float4 zz = z4[i];
        float zv[4] = { zz.x, zz.y, zz.z, zz.w };
#pragma unroll
        for (int k = 0; k < 4; k++) {
            int d = i * 4 + k;
            const float4* wt4 = reinterpret_cast<const float4*>(&sW1[d * 16]);
            const float4* wb4 = reinterpret_cast<const float4*>(&sW1[(128 + d) * 16]);
#pragma unroll
            for (int q = 0; q < 4; q++) {
                float4 wt = wt4[q];
                float4 wb = wb4[q];
                accT[q * 4 + 0] = fmaf(zv[k], wt.x, accT[q * 4 + 0]);
                accT[q * 4 + 1] = fmaf(zv[k], wt.y, accT[q * 4 + 1]);
                accT[q * 4 + 2] = fmaf(zv[k], wt.z, accT[q * 4 + 2]);
                accT[q * 4 + 3] = fmaf(zv[k], wt.w, accT[q * 4 + 3]);
                accB[q * 4 + 0] = fmaf(zv[k], wb.x, accB[q * 4 + 0]);
                accB[q * 4 + 1] = fmaf(zv[k], wb.y, accB[q * 4 + 1]);
                accB[q * 4 + 2] = fmaf(zv[k], wb.z, accB[q * 4 + 2]);
                accB[q * 4 + 3] = fmaf(zv[k], wb.w, accB[q * 4 + 3]);
            }
        }
    }

    float4* P4 = reinterpret_cast<float4*>(g_P) + (size_t)n * 8;
#pragma unroll
    for (int q = 0; q < 4; q++) {
        P4[q]     = make_float4(accT[q*4+0], accT[q*4+1], accT[q*4+2], accT[q*4+3]);
        P4[4 + q] = make_float4(accB[q*4+0], accB[q*4+1], accB[q*4+2], accB[q*4+3]);
    }
}

// ---------------------------------------------------------------------------
// Kernel 2: per-edge work.  4 lanes per edge (lanes contiguous in a warp).
//   - adj_logits = dot(z[row], z[col])          (128 fp32 MACs, split 4 ways)
//   - h = relu(P_top[row] + P_bot[col] + b1)    (16 units, 4 per lane)
//   - weights = softplus(h @ W2 + b2)
// out layout: [adj_logits (E), weights (E)]
// ---------------------------------------------------------------------------
__global__ __launch_bounds__(256)
void edge_kernel(const float* __restrict__ z,
                 const void* __restrict__ ei_raw,   // [2,E] int64 OR int32
                 const float* __restrict__ b1,
                 const float* __restrict__ W2,
                 const float* __restrict__ b2,
                 float* __restrict__ out,
                 int E, int N)
{
    int t   = blockIdx.x * blockDim.x + threadIdx.x;
    int e   = t >> 2;
    int sub = t & 3;
    bool valid = (e < E);
    int ec = valid ? e : (E - 1);   // clamp so all lanes stay active for shuffles

    int row, col;
    if (g_ei_is64) {
        const long long* ei = (const long long*)ei_raw;
        row = (int)ei[ec];
        col = (int)ei[(size_t)E + ec];
    } else {
        const int* ei = (const int*)ei_raw;
        row = ei[ec];
        col = ei[(size_t)E + ec];
    }
    // final safety clamp (branchless; indices should already be in range)
    row = min(max(row, 0), N - 1);
    col = min(max(col, 0), N - 1);

    const float4* zr = reinterpret_cast<const float4*>(z) + (size_t)row * 32;
    const float4* zc = reinterpret_cast<const float4*>(z) + (size_t)col * 32;

    float acc = 0.f;
#pragma unroll
    for (int i = 0; i < 8; i++) {
        float4 a = zr[sub + 4 * i];
        float4 b = zc[sub + 4 * i];
        acc = fmaf(a.x, b.x, acc);
        acc = fmaf(a.y, b.y, acc);
        acc = fmaf(a.z, b.z, acc);
        acc = fmaf(a.w, b.w, acc);
    }
    acc += __shfl_xor_sync(0xffffffffu, acc, 1);
    acc += __shfl_xor_sync(0xffffffffu, acc, 2);

    // MLP: each lane covers 4 hidden units
    const float4* P4 = reinterpret_cast<const float4*>(g_P);
    float4 pr = P4[(size_t)row * 8 + sub];        // top part of P[row]
    float4 pc = P4[(size_t)col * 8 + 4 + sub];    // bottom part of P[col]
    float4 bb = reinterpret_cast<const float4*>(b1)[sub];
    float4 w2 = reinterpret_cast<const float4*>(W2)[sub];

    float h0 = fmaxf(pr.x + pc.x + bb.x, 0.f);
    float h1 = fmaxf(pr.y + pc.y + bb.y, 0.f);
    float h2 = fmaxf(pr.z + pc.z + bb.z, 0.f);
    float h3 = fmaxf(pr.w + pc.w + bb.w, 0.f);

    float part = h0 * w2.x + h1 * w2.y + h2 * w2.z + h3 * w2.w;
    part += __shfl_xor_sync(0xffffffffu, part, 1);
    part += __shfl_xor_sync(0xffffffffu, part, 2);

    if (valid && sub == 0) {
        float x = part + b2[0];
        // numerically stable softplus, matches jax.nn.softplus
        float w = fmaxf(x, 0.f) + log1pf(expf(-fabsf(x)));
        out[e]             = acc;
        out[(size_t)E + e] = w;
    }
}

// ---------------------------------------------------------------------------
// Launch
// ---------------------------------------------------------------------------
extern "C" void kernel_launch(void* const* d_in, const int* in_sizes, int n_in,
                              void* d_out, int out_size)
{
    const float* z  = (const float*)d_in[0];        // [N,128] f32
    const void*  ei = d_in[1];                      // [2,E]   i64 or i32
    const float* W1 = (const float*)d_in[2];        // [256,16] f32
    const float* b1 = (const float*)d_in[3];        // [16]
    const float* W2 = (const float*)d_in[4];        // [16,1]
    const float* b2 = (const float*)d_in[5];        // [1]
    float*       out = (float*)d_out;

    int N = in_sizes[0] / 128;
    int E = in_sizes[1] / 2;

    detect_kernel<<<1, 32>>>((const long long*)ei, E, N);

    int blocks1 = (N + 255) / 256;
    proj_kernel<<<blocks1, 256>>>(z, W1, N);

    long long threads2 = (long long)E * 4;
    int blocks2 = (int)((threads2 + 255) / 256);
    edge_kernel<<<blocks2, 256>>>(z, ei, b1, W2, b2, out, E, N);
}